// round 9
// baseline (speedup 1.0000x reference)
#include <cuda_runtime.h>
#include <math.h>

#define BB 8
#define C4v 64
#define OQ 16
#define NNv 512
#define LL 12
#define CCv (OQ * C4v)   // 1024

typedef unsigned long long ull;

__device__ __forceinline__ ull pk(float lo, float hi) {
    ull r; asm("mov.b64 %0,{%1,%2};" : "=l"(r) : "f"(lo), "f"(hi)); return r;
}
__device__ __forceinline__ void upk(ull v, float& lo, float& hi) {
    asm("mov.b64 {%0,%1},%2;" : "=f"(lo), "=f"(hi) : "l"(v));
}
__device__ __forceinline__ ull fma2(ull a, ull b, ull c) {
    ull d; asm("fma.rn.f32x2 %0,%1,%2,%3;" : "=l"(d) : "l"(a), "l"(b), "l"(c)); return d;
}

// Scratch (device globals: allocation-free per harness rules)
__device__ float g_G[BB * NNv * CCv];   // [b][n][c'][c]  16.8 MB
__device__ float g_Fl[BB * NNv * OQ];   // [b][n][c']
__device__ float g_T[BB * NNv * NNv];   // [b][k][n]      8.4 MB
__device__ float g_H[BB * NNv * CCv];   // [b][k][cc]     16.8 MB
__device__ float g_xx[BB * OQ];
__device__ float g_yy[BB * OQ];
__device__ float g_invl2[BB];

__global__ void k_zero() {
    int t = threadIdx.x;
    if (t < BB * OQ) { g_xx[t] = 0.f; g_yy[t] = 0.f; }
}

// k1: Fc (local), Fl, G, norm partials. Block per (n, b), 128 threads.
__global__ void k1(const float* __restrict__ x, const float* __restrict__ Wc,
                   const float* __restrict__ bc) {
    int n = blockIdx.x, b = blockIdx.y;
    __shared__ float xs[C4v * LL];   // [c][l]
    __shared__ float Ws[OQ * C4v];   // [o][c]
    __shared__ float Fc[OQ * LL];    // [o][l]
    int t = threadIdx.x;

    for (int i = t; i < C4v * LL; i += 128) {
        int c = i / LL, l = i % LL;
        xs[i] = x[((b * C4v + c) * NNv + n) * LL + l];
    }
    for (int i = t; i < OQ * C4v; i += 128) Ws[i] = Wc[i];
    __syncthreads();

    for (int i = t; i < OQ * LL; i += 128) {
        int o = i / LL, l = i % LL;
        float s = bc[o];
        #pragma unroll 16
        for (int c = 0; c < C4v; c++) s += Ws[o * C4v + c] * xs[c * LL + l];
        Fc[i] = s;
    }
    __syncthreads();

    // G[b][n][o][c] = sum_l Fc[o][l] * x[c][l]
    for (int i = t; i < CCv; i += 128) {
        int o = i >> 6, c = i & 63;
        float s = 0.f;
        #pragma unroll
        for (int l = 0; l < LL; l++) s += Fc[o * LL + l] * xs[c * LL + l];
        g_G[(b * NNv + n) * CCv + i] = s;
    }
    if (t < OQ) {
        float fl = Fc[t * LL + (LL - 1)];
        g_Fl[(b * NNv + n) * OQ + t] = fl;
        float ys = 0.f;
        #pragma unroll
        for (int l = 0; l < LL; l++) { float v = Fc[t * LL + l]; ys += v * v; }
        atomicAdd(&g_xx[b * OQ + t], fl * fl);
        atomicAdd(&g_yy[b * OQ + t], ys);
    }
}

// k1b: inv_l2[b] = 1 / sum_c sqrt(xx)*sqrt(yy)
__global__ void k1b() {
    int b = blockIdx.x;
    int t = threadIdx.x;  // 32
    float v = 0.f;
    if (t < OQ) v = sqrtf(g_xx[b * OQ + t]) * sqrtf(g_yy[b * OQ + t]);
    #pragma unroll
    for (int s = 16; s > 0; s >>= 1) v += __shfl_down_sync(0xffffffffu, v, s);
    if (t == 0) g_invl2[b] = 1.0f / v;
}

// k2: T[b][p][q] = relu(tanh(inv * max_c sum_o Fl[b][q][o] * G[b][p][o][c]))
// Scheme B: 64 threads per (p,b). Thread owns 8 q = t + j*64 packed as 4
// q-pair FMA2 chains. G read as scalar LDS.32 (128B broadcast return) + ALU
// dup -> 32B/FMA2-instr crossbar traffic (half budget, crossbar unbound).
__global__ void __launch_bounds__(64) k2() {
    int p = blockIdx.x, b = blockIdx.y;
    __shared__ __align__(16) float Gs[OQ * C4v];  // natural [o][c], 4 KB
    int t = threadIdx.x;  // 64

    {
        const float4* gsrc = (const float4*)(g_G + ((size_t)b * NNv + p) * CCv);
        #pragma unroll
        for (int i = t; i < CCv / 4; i += 64) ((float4*)Gs)[i] = gsrc[i];
    }

    // Fl packs: chain r covers q = t + 2r*64 (lo lane), t + (2r+1)*64 (hi).
    ull fd[4][OQ];
    #pragma unroll
    for (int r = 0; r < 4; r++) {
        const float4* plo =
            (const float4*)(g_Fl + ((size_t)b * NNv + t + (2 * r) * 64) * OQ);
        const float4* phi =
            (const float4*)(g_Fl + ((size_t)b * NNv + t + (2 * r + 1) * 64) * OQ);
        #pragma unroll
        for (int i = 0; i < 4; i++) {
            float4 vl = __ldg(plo + i);
            float4 vh = __ldg(phi + i);
            fd[r][4 * i + 0] = pk(vl.x, vh.x);
            fd[r][4 * i + 1] = pk(vl.y, vh.y);
            fd[r][4 * i + 2] = pk(vl.z, vh.z);
            fd[r][4 * i + 3] = pk(vl.w, vh.w);
        }
    }
    __syncthreads();

    float inv = g_invl2[b];
    float m[8];
    #pragma unroll
    for (int j = 0; j < 8; j++) m[j] = -1e30f;

    #pragma unroll 2
    for (int c = 0; c < C4v; c++) {
        ull a0 = 0, a1 = 0, a2 = 0, a3 = 0;
        #pragma unroll
        for (int o = 0; o < OQ; o++) {
            float g = Gs[o * C4v + c];   // uniform scalar LDS.32 (broadcast)
            ull gd = pk(g, g);           // ALU dup (idle pipe)
            a0 = fma2(fd[0][o], gd, a0);
            a1 = fma2(fd[1][o], gd, a1);
            a2 = fma2(fd[2][o], gd, a2);
            a3 = fma2(fd[3][o], gd, a3);
        }
        float lo, hi;
        upk(a0, lo, hi); m[0] = fmaxf(m[0], lo); m[1] = fmaxf(m[1], hi);
        upk(a1, lo, hi); m[2] = fmaxf(m[2], lo); m[3] = fmaxf(m[3], hi);
        upk(a2, lo, hi); m[4] = fmaxf(m[4], lo); m[5] = fmaxf(m[5], hi);
        upk(a3, lo, hi); m[6] = fmaxf(m[6], lo); m[7] = fmaxf(m[7], hi);
    }
    float* Trow = g_T + ((size_t)b * NNv + p) * NNv + t;
    #pragma unroll
    for (int j = 0; j < 8; j++)
        Trow[j * 64] = fmaxf(tanhf(m[j] * inv), 0.f);
}

// k3: per-b SGEMM  H[k][cc] = sum_n T[k][n] * G[n][cc]
// 128x128 tile, Kt=16, 256 threads, 8x8 microtile (cc split 4+4), B staged
// untransposed Bs[k][nn] (broadcast scalar reads). Double-buffered smem.
// 256 CTAs at 2/SM = one full wave.
__global__ void __launch_bounds__(256, 2) k3() {
    int b = blockIdx.z;
    int cc0 = blockIdx.y * 128;
    int k0 = blockIdx.x * 128;
    const float* A  = g_G + (size_t)b * NNv * CCv;  // [n][cc]
    const float* Bm = g_T + (size_t)b * NNv * NNv;  // [k][n]
    float* Cm = g_H + (size_t)b * NNv * CCv;        // [k][cc]

    __shared__ float As[2][16][128];
    __shared__ float Bs[2][128][21];
    int t = threadIdx.x;
    int tx = t & 15, ty = t >> 4;   // tx -> cc (4+4), ty -> k (8)

    int r_arow = t >> 5, r_acol = (t & 31) * 4;
    int r_arow2 = (t + 256) >> 5, r_acol2 = ((t + 256) & 31) * 4;
    int r_bk = t >> 2, r_bn = (t & 3) * 4;
    int r_bk2 = (t + 256) >> 2, r_bn2 = ((t + 256) & 3) * 4;

    // stage tile 0 into buffer 0
    {
        *(float4*)(&As[0][r_arow][r_acol]) =
            *(const float4*)(A + (size_t)r_arow * CCv + cc0 + r_acol);
        *(float4*)(&As[0][r_arow2][r_acol2]) =
            *(const float4*)(A + (size_t)r_arow2 * CCv + cc0 + r_acol2);
        float4 v = *(const float4*)(Bm + (size_t)(k0 + r_bk) * NNv + r_bn);
        Bs[0][r_bk][r_bn + 0] = v.x; Bs[0][r_bk][r_bn + 1] = v.y;
        Bs[0][r_bk][r_bn + 2] = v.z; Bs[0][r_bk][r_bn + 3] = v.w;
        v = *(const float4*)(Bm + (size_t)(k0 + r_bk2) * NNv + r_bn2);
        Bs[0][r_bk2][r_bn2 + 0] = v.x; Bs[0][r_bk2][r_bn2 + 1] = v.y;
        Bs[0][r_bk2][r_bn2 + 2] = v.z; Bs[0][r_bk2][r_bn2 + 3] = v.w;
    }
    __syncthreads();

    ull acc[4][8];
    #pragma unroll
    for (int i = 0; i < 4; i++)
        #pragma unroll
        for (int j = 0; j < 8; j++) acc[i][j] = 0ull;

    int buf = 0;
    for (int n0 = 0; n0 < NNv; n0 += 16) {
        if (n0 + 16 < NNv) {
            int nb = buf ^ 1, nn0 = n0 + 16;
            *(float4*)(&As[nb][r_arow][r_acol]) =
                *(const float4*)(A + (size_t)(nn0 + r_arow) * CCv + cc0 + r_acol);
            *(float4*)(&As[nb][r_arow2][r_acol2]) =
                *(const float4*)(A + (size_t)(nn0 + r_arow2) * CCv + cc0 + r_acol2);
            float4 v = *(const float4*)(Bm + (size_t)(k0 + r_bk) * NNv + nn0 + r_bn);
            Bs[nb][r_bk][r_bn + 0] = v.x; Bs[nb][r_bk][r_bn + 1] = v.y;
            Bs[nb][r_bk][r_bn + 2] = v.z; Bs[nb][r_bk][r_bn + 3] = v.w;
            v = *(const float4*)(Bm + (size_t)(k0 + r_bk2) * NNv + nn0 + r_bn2);
            Bs[nb][r_bk2][r_bn2 + 0] = v.x; Bs[nb][r_bk2][r_bn2 + 1] = v.y;
            Bs[nb][r_bk2][r_bn2 + 2] = v.z; Bs[nb][r_bk2][r_bn2 + 3] = v.w;
        }
        #pragma unroll
        for (int kk = 0; kk < 16; kk++) {
            float4 aA = *(const float4*)(&As[buf][kk][tx * 4]);
            float4 aB = *(const float4*)(&As[buf][kk][64 + tx * 4]);
            ull a0 = pk(aA.x, aA.y), a1 = pk(aA.z, aA.w);
            ull a2 = pk(aB.x, aB.y), a3 = pk(aB.z, aB.w);
            #pragma unroll
            for (int j = 0; j < 8; j++) {
                float bv = Bs[buf][ty * 8 + j][kk];               // broadcast
                ull bp = pk(bv, bv);
                acc[0][j] = fma2(a0, bp, acc[0][j]);
                acc[1][j] = fma2(a1, bp, acc[1][j]);
                acc[2][j] = fma2(a2, bp, acc[2][j]);
                acc[3][j] = fma2(a3, bp, acc[3][j]);
            }
        }
        __syncthreads();
        buf ^= 1;
    }
    #pragma unroll
    for (int j = 0; j < 8; j++) {
        float4 v0, v1;
        upk(acc[0][j], v0.x, v0.y); upk(acc[1][j], v0.z, v0.w);
        upk(acc[2][j], v1.x, v1.y); upk(acc[3][j], v1.z, v1.w);
        float* dst = Cm + (size_t)(k0 + ty * 8 + j) * CCv + cc0;
        *(float4*)(dst + tx * 4) = v0;
        *(float4*)(dst + 64 + tx * 4) = v1;
    }
}

// k4: xg[c] = inv * sum_o Fl[k][o] * H[k][o*64+c];
//     out[b][o][k] = b_gcn[o] + sum_c W_gcn[o][c] * xg[c]
__global__ void k4(const float* __restrict__ Wg, const float* __restrict__ bg,
                   float* __restrict__ out) {
    int k = blockIdx.x, b = blockIdx.y;
    __shared__ float Hs[CCv];
    __shared__ float xg[C4v];
    __shared__ float Wgs[C4v * C4v];
    __shared__ float Flk[OQ];
    int t = threadIdx.x;  // 128

    for (int i = t; i < CCv / 4; i += 128)
        ((float4*)Hs)[i] = ((const float4*)(g_H + ((size_t)b * NNv + k) * CCv))[i];
    for (int i = t; i < C4v * C4v / 4; i += 128)
        ((float4*)Wgs)[i] = ((const float4*)Wg)[i];
    if (t < OQ) Flk[t] = g_Fl[((size_t)b * NNv + k) * OQ + t];
    __syncthreads();

    float inv = g_invl2[b];
    if (t < C4v) {
        float s = 0.f;
        #pragma unroll
        for (int o = 0; o < OQ; o++) s += Flk[o] * Hs[o * C4v + t];
        xg[t] = s * inv;
    }
    __syncthreads();
    if (t < C4v) {
        float s = bg[t];
        #pragma unroll 16
        for (int c = 0; c < C4v; c++) s += Wgs[t * C4v + c] * xg[c];
        out[((size_t)b * C4v + t) * NNv + k] = s;
    }
}

extern "C" void kernel_launch(void* const* d_in, const int* in_sizes, int n_in,
                              void* d_out, int out_size) {
    const float* x  = (const float*)d_in[0];
    const float* Wc = (const float*)d_in[1];
    const float* bc = (const float*)d_in[2];
    const float* Wg = (const float*)d_in[3];
    const float* bg = (const float*)d_in[4];
    float* out = (float*)d_out;

    k_zero<<<1, 256>>>();
    k1<<<dim3(NNv, BB), 128>>>(x, Wc, bc);
    k1b<<<BB, 32>>>();
    k2<<<dim3(NNv, BB), 64>>>();
    k3<<<dim3(NNv / 128, CCv / 128, BB), 256>>>();
    k4<<<dim3(NNv, BB), 128>>>(Wg, bg, out);
}